// round 15
// baseline (speedup 1.0000x reference)
#include <cuda_runtime.h>
#include <cuda_fp16.h>
#include <cstdint>

#define B_ 8
#define T_ 4096
#define CE 1024
#define HD 64
#define SCALE 0.125f

typedef unsigned long long u64;
typedef unsigned int u32;

// ---- device scratch (allocation-free) ----
__device__ __align__(16) float g_v[B_ * T_ * HD];
__device__ __align__(16) __half g_wtf[3 * HD * CE];         // W^T fp16 [n][k]
__device__ __align__(16) __half g_qf[B_ * T_ * HD];         // q/8 fp16
__device__ __align__(16) __half g_kf[B_ * T_ * HD];         // k fp16
__device__ __align__(16) __half g_vtf[B_ * HD * T_];        // (V*dinv)^T fp16
__device__ __align__(16) float g_dp[B_ * 32 * T_];
__device__ __align__(16) float g_op[4 * B_ * T_ * HD];

__device__ __forceinline__ float fast_exp(float x) {
    float y = x * 1.4426950408889634f;
    float n = rintf(y);
    float f = y - n;
    float p = 1.3333558146e-3f;
    p = fmaf(p, f, 9.6181291076e-3f);
    p = fmaf(p, f, 5.5504108664e-2f);
    p = fmaf(p, f, 2.4022650696e-1f);
    p = fmaf(p, f, 6.9314718056e-1f);
    p = fmaf(p, f, 1.0f);
    return p * __int_as_float(((int)n + 127) << 23);
}

// ---- warp MMA helpers ----
__device__ __forceinline__ u32 s2u(const void* p) {
    u32 a;
    asm("{ .reg .u64 t; cvta.to.shared.u64 t, %1; cvt.u32.u64 %0, t; }"
        : "=r"(a) : "l"(p));
    return a;
}
__device__ __forceinline__ void ldsm4(u32* r, u32 addr) {
    asm volatile("ldmatrix.sync.aligned.m8n8.x4.shared.b16 {%0,%1,%2,%3}, [%4];"
                 : "=r"(r[0]), "=r"(r[1]), "=r"(r[2]), "=r"(r[3]) : "r"(addr));
}
__device__ __forceinline__ void mma16816h(float* d, const u32* a, const u32* b) {
    asm volatile(
        "mma.sync.aligned.m16n8k16.row.col.f32.f16.f16.f32 "
        "{%0,%1,%2,%3}, {%4,%5,%6,%7}, {%8,%9}, {%0,%1,%2,%3};"
        : "+f"(d[0]), "+f"(d[1]), "+f"(d[2]), "+f"(d[3])
        : "r"(a[0]), "r"(a[1]), "r"(a[2]), "r"(a[3]), "r"(b[0]), "r"(b[1]));
}

// ---------------------------------------------------------------------------
// Pass 0: transpose W into [n=192][k=1024] fp16
// ---------------------------------------------------------------------------
__global__ __launch_bounds__(256) void wsplit_kernel(
    const float* __restrict__ Wq, const float* __restrict__ Wk,
    const float* __restrict__ Wv) {
    int i = blockIdx.x * 256 + threadIdx.x;
    int n = i >> 10, k = i & 1023;
    const float* W = (n < 64) ? Wq : (n < 128) ? Wk : Wv;
    g_wtf[i] = __float2half_rn(W[k * HD + (n & 63)]);
}

// ---------------------------------------------------------------------------
// Pass 1: proj via f16 mma 2-pass (Xh·W + Xl·W), fused x fp32->fp16 hi/lo.
// Epilogue: q/8 -> fp16; k -> fp16; v -> fp32.
// ---------------------------------------------------------------------------
#define PXH 0
#define PXL (128 * 144)
#define PWF (2 * 128 * 144)
#define SMP_TOTAL (PWF + 64 * 144)   // 46080

__global__ __launch_bounds__(256) void proj_mma_kernel(const float* __restrict__ x) {
    extern __shared__ __align__(16) char smem[];
    int ntile = blockIdx.x, m0 = blockIdx.y << 7;
    int t = threadIdx.x, wid = t >> 5, lane = t & 31;
    int qw = wid >> 1, hw = wid & 1;
    u32 sb = s2u(smem);

    float acc[2][4][4] = {};
#pragma unroll 1
    for (int kc = 0; kc < 16; kc++) {
        int k0 = kc << 6;
        __syncthreads();
#pragma unroll
        for (int rep = 0; rep < 8; rep++) {
            int li = rep * 256 + t;
            int row = li >> 4, c4 = li & 15;
            float4 v = *(const float4*)&x[(size_t)(m0 + row) * CE + k0 + c4 * 4];
            __half2 h01 = __floats2half2_rn(v.x, v.y);
            __half2 h23 = __floats2half2_rn(v.z, v.w);
            __half2 l01 = __floats2half2_rn(v.x - __half2float(h01.x),
                                            v.y - __half2float(h01.y));
            __half2 l23 = __floats2half2_rn(v.z - __half2float(h23.x),
                                            v.w - __half2float(h23.y));
            *(__half2*)(smem + PXH + row * 144 + c4 * 8) = h01;
            *(__half2*)(smem + PXH + row * 144 + c4 * 8 + 4) = h23;
            *(__half2*)(smem + PXL + row * 144 + c4 * 8) = l01;
            *(__half2*)(smem + PXL + row * 144 + c4 * 8 + 4) = l23;
        }
#pragma unroll
        for (int rep = 0; rep < 2; rep++) {
            int li = rep * 256 + t;
            int row = li >> 3, c16 = li & 7;
            *(uint4*)(smem + PWF + row * 144 + c16 * 16) = *(const uint4*)
                &g_wtf[(size_t)(ntile * 64 + row) * CE + k0 + c16 * 8];
        }
        __syncthreads();

#pragma unroll
        for (int kk = 0; kk < 4; kk++) {
            u32 ah[2][4], al[2][4];
#pragma unroll
            for (int tq = 0; tq < 2; tq++) {
                u32 aoff = (u32)((qw * 32 + tq * 16 + (lane & 15)) * 144 +
                                 (kk * 16 + ((lane >> 4) << 3)) * 2);
                ldsm4(ah[tq], sb + PXH + aoff);
                ldsm4(al[tq], sb + PXL + aoff);
            }
            u32 bf[2][4];
#pragma unroll
            for (int ng = 0; ng < 2; ng++) {
                u32 roff = (u32)((hw * 32 + ng * 16 + (lane & 7) +
                                  ((lane & 16) ? 8 : 0)) * 144 +
                                 (kk * 16 + ((lane & 8) ? 8 : 0)) * 2);
                ldsm4(bf[ng], sb + PWF + roff);
            }
#pragma unroll
            for (int tq = 0; tq < 2; tq++)
#pragma unroll
                for (int nt = 0; nt < 4; nt++) {
                    const u32* bb = bf[nt >> 1] + (nt & 1) * 2;
                    mma16816h(acc[tq][nt], ah[tq], bb);
                    mma16816h(acc[tq][nt], al[tq], bb);
                }
        }
    }

    int g = lane >> 2, tp = (lane & 3) << 1;
#pragma unroll
    for (int tq = 0; tq < 2; tq++) {
        int mA = m0 + qw * 32 + tq * 16 + g;
        int mB = mA + 8;
#pragma unroll
        for (int nt = 0; nt < 4; nt++) {
            int h = hw * 32 + nt * 8 + tp;
            float v0 = acc[tq][nt][0], v1 = acc[tq][nt][1];
            float v2 = acc[tq][nt][2], v3 = acc[tq][nt][3];
            if (ntile == 2) {
                *(float2*)&g_v[(size_t)mA * HD + h] = make_float2(v0, v1);
                *(float2*)&g_v[(size_t)mB * HD + h] = make_float2(v2, v3);
            } else {
                __half* dst = (ntile == 0) ? g_qf : g_kf;
                if (ntile == 0) {
                    v0 *= SCALE; v1 *= SCALE; v2 *= SCALE; v3 *= SCALE;
                }
                *(__half2*)&dst[(size_t)mA * HD + h] = __floats2half2_rn(v0, v1);
                *(__half2*)&dst[(size_t)mB * HD + h] = __floats2half2_rn(v2, v3);
            }
        }
    }
}

// ---------------------------------------------------------------------------
// Pass 2: score (stats-only). QK f16 mma + exp + fp16-round + column sums.
// NO E store — out recomputes E bitwise-identically.
// ---------------------------------------------------------------------------
#define OQF 0
#define OKF (128 * 144)
#define OBUF (2 * 128 * 144)
#define SMM_TOTAL (OBUF + 4 * 128 * 4)   // 38912

__global__ __launch_bounds__(256) void score_mma_kernel() {
    extern __shared__ __align__(16) char smem[];
    int b = blockIdx.y;
    int ti = blockIdx.x;
    int qt = (int)((sqrtf(8.f * (float)ti + 1.f) - 1.f) * 0.5f);
    while ((qt + 1) * (qt + 2) / 2 <= ti) qt++;
    while (qt * (qt + 1) / 2 > ti) qt--;
    int kt = ti - qt * (qt + 1) / 2;
    int q0 = qt << 7, k0 = kt << 7;
    int t = threadIdx.x, wid = t >> 5, lane = t & 31;

    {   // stage Qf + Kf
        int a = t >> 7, row = t & 127;
        const __half* src = (a == 0) ? g_qf + (size_t)(b * T_ + q0) * HD
                                     : g_kf + (size_t)(b * T_ + k0) * HD;
        const uint4* s = (const uint4*)(src + (size_t)row * HD);
        uint4* d = (uint4*)(smem + (a == 0 ? OQF : OKF) + row * 144);
#pragma unroll
        for (int c = 0; c < 8; c++) d[c] = s[c];
    }
    __syncthreads();

    int qw = wid >> 1, kw = wid & 1;
    u32 sb = s2u(smem);
    float acc[2][8][4] = {};

#pragma unroll
    for (int kk = 0; kk < 4; kk++) {
        u32 af[2][4];
#pragma unroll
        for (int tq = 0; tq < 2; tq++) {
            u32 aoff = (u32)((qw * 32 + tq * 16 + (lane & 15)) * 144 +
                             (kk * 16 + ((lane >> 4) << 3)) * 2);
            ldsm4(af[tq], sb + OQF + aoff);
        }
        u32 bf[4][4];
#pragma unroll
        for (int ng = 0; ng < 4; ng++) {
            u32 roff = (u32)((kw * 64 + ng * 16 + (lane & 7) +
                              ((lane & 16) ? 8 : 0)) * 144 +
                             (kk * 16 + ((lane & 8) ? 8 : 0)) * 2);
            ldsm4(bf[ng], sb + OKF + roff);
        }
#pragma unroll
        for (int tq = 0; tq < 2; tq++)
#pragma unroll
            for (int ng = 0; ng < 4; ng++)
#pragma unroll
                for (int hf = 0; hf < 2; hf++)
                    mma16816h(acc[tq][ng * 2 + hf], af[tq], bf[ng] + hf * 2);
    }

    int g = lane >> 2, tp = (lane & 3) << 1;
    bool diag = (kt == qt);
    float cs[8][2] = {};
#pragma unroll
    for (int tq = 0; tq < 2; tq++) {
        int rA = qw * 32 + tq * 16 + g;
        int rB = rA + 8;
#pragma unroll
        for (int nt = 0; nt < 8; nt++) {
            int col = kw * 64 + nt * 8 + tp;
            float e0 = fast_exp(acc[tq][nt][0]);
            float e1 = fast_exp(acc[tq][nt][1]);
            float e2 = fast_exp(acc[tq][nt][2]);
            float e3 = fast_exp(acc[tq][nt][3]);
            if (diag) {
                if (q0 + rA < k0 + col) e0 = 0.f;
                if (q0 + rA < k0 + col + 1) e1 = 0.f;
                if (q0 + rB < k0 + col) e2 = 0.f;
                if (q0 + rB < k0 + col + 1) e3 = 0.f;
            }
            // round through fp16 to match out's E quantization exactly
            __half2 hA = __floats2half2_rn(e0, e1);
            __half2 hB = __floats2half2_rn(e2, e3);
            cs[nt][0] += __half2float(hA.x) + __half2float(hB.x);
            cs[nt][1] += __half2float(hA.y) + __half2float(hB.y);
        }
    }
#pragma unroll
    for (int nt = 0; nt < 8; nt++)
#pragma unroll
        for (int j = 0; j < 2; j++) {
            float v = cs[nt][j];
            v += __shfl_xor_sync(0xffffffffu, v, 4);
            v += __shfl_xor_sync(0xffffffffu, v, 8);
            v += __shfl_xor_sync(0xffffffffu, v, 16);
            cs[nt][j] = v;
        }
    float* buf = (float*)(smem + OBUF);
    __syncthreads();   // staging reads done before buf reuse
    if (lane < 4) {
#pragma unroll
        for (int nt = 0; nt < 8; nt++) {
            buf[qw * 128 + kw * 64 + nt * 8 + ((lane & 3) << 1) + 0] = cs[nt][0];
            buf[qw * 128 + kw * 64 + nt * 8 + ((lane & 3) << 1) + 1] = cs[nt][1];
        }
    }
    __syncthreads();
    if (t < 128) {
        float s = buf[t] + buf[128 + t] + buf[256 + t] + buf[384 + t];
        g_dp[(size_t)((b << 5) + qt) * T_ + k0 + t] = s;
    }
}

// ---------------------------------------------------------------------------
// Pass 3: vprep with fused dinv: Vt = (V/d)^T fp16, [b][h][k]
// ---------------------------------------------------------------------------
__global__ __launch_bounds__(256) void vprep_kernel() {
    __shared__ __align__(16) float Vt[64][68];
    __shared__ float dinv_s[64];
    int k0 = blockIdx.x << 6, b = blockIdx.y;
    int t = threadIdx.x;

    if (t < 64) {
        int k = k0 + t;
        float s = 0.f;
        for (int qt = (k >> 7); qt < 32; qt++)
            s += g_dp[(size_t)((b << 5) + qt) * T_ + k];
        dinv_s[t] = 1.0f / s;
    }
    __syncthreads();
    {
        int k = t >> 2, hseg = (t & 3) << 4;
        float dinv = dinv_s[k];
        const float* src = &g_v[(size_t)(b * T_ + k0 + k) * HD + hseg];
#pragma unroll
        for (int u = 0; u < 4; u++) {
            float4 v = *(const float4*)&src[u * 4];
            Vt[hseg + u * 4 + 0][k] = v.x * dinv;
            Vt[hseg + u * 4 + 1][k] = v.y * dinv;
            Vt[hseg + u * 4 + 2][k] = v.z * dinv;
            Vt[hseg + u * 4 + 3][k] = v.w * dinv;
        }
    }
    __syncthreads();
    {
        int h = t >> 2, kseg = (t & 3) << 4;
        size_t dst = (size_t)(b * HD + h) * T_ + k0 + kseg;
#pragma unroll
        for (int u = 0; u < 4; u++) {
            __half2 p0 = __floats2half2_rn(Vt[h][kseg + u * 4 + 0],
                                           Vt[h][kseg + u * 4 + 1]);
            __half2 p1 = __floats2half2_rn(Vt[h][kseg + u * 4 + 2],
                                           Vt[h][kseg + u * 4 + 3]);
            *(__half2*)&g_vtf[dst + u * 4 + 0] = p0;
            *(__half2*)&g_vtf[dst + u * 4 + 2] = p1;
        }
    }
}

// ---------------------------------------------------------------------------
// Pass 4: out with E recompute: per 64-k chunk, S=Qf·Kf (bitwise == score),
// exp+mask -> smem E fp16 -> E @ Vtf. k-slice grid (32, 4, 8).
// ---------------------------------------------------------------------------
#define OQ2 0
#define OK2 (128 * 144)
#define OV2 (OK2 + 64 * 144)
#define OE2 (OV2 + 64 * 144)
#define SMO_TOTAL (OE2 + 128 * 144)   // 55296

__global__ __launch_bounds__(256) void out_mma_kernel() {
    extern __shared__ __align__(16) char smem[];
    int qt = blockIdx.x, s = blockIdx.y, b = blockIdx.z;
    int q0 = qt << 7;
    int nch = 2 * qt + 2;
    int lo = (s * nch) >> 2, hi = ((s + 1) * nch) >> 2;
    int t = threadIdx.x, wid = t >> 5, lane = t & 31;
    int qw = wid >> 1, kw = wid & 1;
    u32 sb = s2u(smem);
    int g = lane >> 2, tp = (lane & 3) << 1;

    // stage Q once (q/8 fp16): 128 rows x 8 uint4
#pragma unroll
    for (int rep = 0; rep < 4; rep++) {
        int li = rep * 256 + t;
        int row = li >> 3, c16 = li & 7;
        *(uint4*)(smem + OQ2 + row * 144 + c16 * 16) = *(const uint4*)
            &g_qf[(size_t)(b * T_ + q0 + row) * HD + c16 * 8];
    }

    float acc[2][4][4] = {};
    for (int c = lo; c < hi; c++) {
        int k0 = c << 6;
        __syncthreads();
        // stage K chunk (64 rows x 64 h) and V chunk (64 h-rows x 64 k)
        {
            int li = t;
#pragma unroll
            for (int rep = 0; rep < 2; rep++) {
                int row = li >> 3, c16 = li & 7;
                *(uint4*)(smem + OK2 + row * 144 + c16 * 16) = *(const uint4*)
                    &g_kf[(size_t)(b * T_ + k0 + row) * HD + c16 * 8];
                *(uint4*)(smem + OV2 + row * 144 + c16 * 16) = *(const uint4*)
                    &g_vtf[(size_t)(b * HD + row) * T_ + k0 + c16 * 8];
                li += 256;
            }
        }
        __syncthreads();

        // QK mma: warps qw(4 q) x kw(2 k of 32)
        float accs[2][4][4] = {};
#pragma unroll
        for (int kk = 0; kk < 4; kk++) {
            u32 af[2][4];
#pragma unroll
            for (int tq = 0; tq < 2; tq++) {
                u32 aoff = (u32)((qw * 32 + tq * 16 + (lane & 15)) * 144 +
                                 (kk * 16 + ((lane >> 4) << 3)) * 2);
                ldsm4(af[tq], sb + OQ2 + aoff);
            }
            u32 bk[2][4];
#pragma unroll
            for (int ng = 0; ng < 2; ng++) {
                u32 roff = (u32)((kw * 32 + ng * 16 + (lane & 7) +
                                  ((lane & 16) ? 8 : 0)) * 144 +
                                 (kk * 16 + ((lane & 8) ? 8 : 0)) * 2);
                ldsm4(bk[ng], sb + OK2 + roff);
            }
#pragma unroll
            for (int tq = 0; tq < 2; tq++)
#pragma unroll
                for (int nt = 0; nt < 4; nt++)
                    mma16816h(accs[tq][nt], af[tq], bk[nt >> 1] + (nt & 1) * 2);
        }

        // exp + mask -> smem E (fp16)
        bool anymask = (k0 + 63 > q0);
#pragma unroll
        for (int tq = 0; tq < 2; tq++) {
            int rA = qw * 32 + tq * 16 + g;
            int rB = rA + 8;
#pragma unroll
            for (int nt = 0; nt < 4; nt++) {
                int col = kw * 32 + nt * 8 + tp;
                float e0 = fast_exp(accs[tq][nt][0]);
                float e1 = fast_exp(accs[tq][nt][1]);
                float e2 = fast_exp(accs[tq][nt][2]);
                float e3 = fast_exp(accs[tq][nt][3]);
                if (anymask) {
                    if (q0 + rA < k0 + col) e0 = 0.f;
                    if (q0 + rA < k0 + col + 1) e1 = 0.f;
                    if (q0 + rB < k0 + col) e2 = 0.f;
                    if (q0 + rB < k0 + col + 1) e3 = 0.f;
                }
                *(__half2*)(smem + OE2 + rA * 144 + col * 2) =
                    __floats2half2_rn(e0, e1);
                *(__half2*)(smem + OE2 + rB * 144 + col * 2) =
                    __floats2half2_rn(e2, e3);
            }
        }
        __syncthreads();

        // EV mma: warps qw(4 q) x kw(2 h of 32); E is A, Vt is B
#pragma unroll
        for (int kk = 0; kk < 4; kk++) {
            u32 af[2][4];
#pragma unroll
            for (int tq = 0; tq < 2; tq++) {
                u32 aoff = (u32)((qw * 32 + tq * 16 + (lane & 15)) * 144 +
                                 (kk * 16 + ((lane >> 4) << 3)) * 2);
                ldsm4(af[tq], sb + OE2 + aoff);
            }
            u32 bf[2][4];
#pragma unroll
            for (int ng = 0; ng < 2; ng++) {
                u32 roff = (u32)((kw * 32 + ng * 16 + (lane & 7) +
                                  ((lane & 16) ? 8 : 0)) * 144 +
                                 (kk * 16 + ((lane & 8) ? 8 : 0)) * 2);
                ldsm4(bf[ng], sb + OV2 + roff);
            }
#pragma unroll
            for (int tq = 0; tq < 2; tq++)
#pragma unroll
                for (int nt = 0; nt < 4; nt++)
                    mma16816h(acc[tq][nt], af[tq], bf[nt >> 1] + (nt & 1) * 2);
        }
    }

#pragma unroll
    for (int tq = 0; tq < 2; tq++) {
        int qrA = q0 + qw * 32 + tq * 16 + g;
#pragma unroll
        for (int nt = 0; nt < 4; nt++) {
            int h = kw * 32 + nt * 8 + tp;
            size_t base = (size_t)((s * B_ + b) * T_);
            *(float2*)&g_op[(base + qrA) * HD + h] =
                make_float2(acc[tq][nt][0], acc[tq][nt][1]);
            *(float2*)&g_op[(base + qrA + 8) * HD + h] =
                make_float2(acc[tq][nt][2], acc[tq][nt][3]);
        }
    }
}

// ---------------------------------------------------------------------------
// Pass 5: sum 4 split partials
// ---------------------------------------------------------------------------
__global__ void reduce_kernel(float* __restrict__ out) {
    const int N4 = B_ * T_ * HD / 4;
    int i = blockIdx.x * 256 + threadIdx.x;
    const float4* p = (const float4*)g_op;
    float4 a = p[i], b = p[i + N4], c = p[i + 2 * N4], d = p[i + 3 * N4];
    ((float4*)out)[i] = make_float4(a.x + b.x + c.x + d.x,
                                    a.y + b.y + c.y + d.y,
                                    a.z + b.z + c.z + d.z,
                                    a.w + b.w + c.w + d.w);
}

// ---------------------------------------------------------------------------
// inputs: x, Wk, Wq, Wv ; output fp32 [8,4096,64]
// ---------------------------------------------------------------------------
extern "C" void kernel_launch(void* const* d_in, const int* in_sizes, int n_in,
                              void* d_out, int out_size) {
    const float* x  = (const float*)d_in[0];
    const float* Wk = (const float*)d_in[1];
    const float* Wq = (const float*)d_in[2];
    const float* Wv = (const float*)d_in[3];
    float* out = (float*)d_out;

    cudaFuncSetAttribute(proj_mma_kernel,
        cudaFuncAttributeMaxDynamicSharedMemorySize, SMP_TOTAL);
    cudaFuncSetAttribute(score_mma_kernel,
        cudaFuncAttributeMaxDynamicSharedMemorySize, SMM_TOTAL);
    cudaFuncSetAttribute(out_mma_kernel,
        cudaFuncAttributeMaxDynamicSharedMemorySize, SMO_TOTAL);

    wsplit_kernel<<<768, 256>>>(Wq, Wk, Wv);
    proj_mma_kernel<<<dim3(3, 256), 256, SMP_TOTAL>>>(x);
    score_mma_kernel<<<dim3(528, 8), 256, SMM_TOTAL>>>();
    vprep_kernel<<<dim3(64, 8), 256>>>();
    out_mma_kernel<<<dim3(32, 4, 8), 256, SMO_TOTAL>>>();
    reduce_kernel<<<2048, 256>>>(out);
}

// round 16
// speedup vs baseline: 1.1707x; 1.1707x over previous
#include <cuda_runtime.h>
#include <cuda_fp16.h>
#include <cstdint>

#define B_ 8
#define T_ 4096
#define CE 1024
#define HD 64
#define SCALE 0.125f

typedef unsigned long long u64;
typedef unsigned int u32;

// ---- device scratch (allocation-free) ----
__device__ __align__(16) float g_v[B_ * T_ * HD];
__device__ __align__(16) __half g_wtf[3 * HD * CE];         // W^T fp16 [n][k]
__device__ __align__(16) __half g_qf[B_ * T_ * HD];         // q/8 fp16
__device__ __align__(16) __half g_kf[B_ * T_ * HD];         // k fp16
__device__ __align__(16) __half g_ef[(size_t)B_ * T_ * T_]; // E fp16
__device__ __align__(16) __half g_vtf[B_ * HD * T_];        // (V*dinv)^T fp16
__device__ __align__(16) float g_dp[B_ * 32 * T_];
__device__ __align__(16) float g_op[4 * B_ * T_ * HD];

__device__ __forceinline__ float fast_exp(float x) {
    float y = x * 1.4426950408889634f;
    float n = rintf(y);
    float f = y - n;
    float p = 1.3333558146e-3f;
    p = fmaf(p, f, 9.6181291076e-3f);
    p = fmaf(p, f, 5.5504108664e-2f);
    p = fmaf(p, f, 2.4022650696e-1f);
    p = fmaf(p, f, 6.9314718056e-1f);
    p = fmaf(p, f, 1.0f);
    return p * __int_as_float(((int)n + 127) << 23);
}

// ---- warp MMA helpers ----
__device__ __forceinline__ u32 s2u(const void* p) {
    u32 a;
    asm("{ .reg .u64 t; cvta.to.shared.u64 t, %1; cvt.u32.u64 %0, t; }"
        : "=r"(a) : "l"(p));
    return a;
}
__device__ __forceinline__ void ldsm4(u32* r, u32 addr) {
    asm volatile("ldmatrix.sync.aligned.m8n8.x4.shared.b16 {%0,%1,%2,%3}, [%4];"
                 : "=r"(r[0]), "=r"(r[1]), "=r"(r[2]), "=r"(r[3]) : "r"(addr));
}
__device__ __forceinline__ void mma16816h(float* d, const u32* a, const u32* b) {
    asm volatile(
        "mma.sync.aligned.m16n8k16.row.col.f32.f16.f16.f32 "
        "{%0,%1,%2,%3}, {%4,%5,%6,%7}, {%8,%9}, {%0,%1,%2,%3};"
        : "+f"(d[0]), "+f"(d[1]), "+f"(d[2]), "+f"(d[3])
        : "r"(a[0]), "r"(a[1]), "r"(a[2]), "r"(a[3]), "r"(b[0]), "r"(b[1]));
}

// ---------------------------------------------------------------------------
// Pass 0: transpose W into [n=192][k=1024] fp16
// ---------------------------------------------------------------------------
__global__ __launch_bounds__(256) void wsplit_kernel(
    const float* __restrict__ Wq, const float* __restrict__ Wk,
    const float* __restrict__ Wv) {
    int i = blockIdx.x * 256 + threadIdx.x;
    int n = i >> 10, k = i & 1023;
    const float* W = (n < 64) ? Wq : (n < 128) ? Wk : Wv;
    g_wtf[i] = __float2half_rn(W[k * HD + (n & 63)]);
}

// ---------------------------------------------------------------------------
// Pass 1: proj via f16 mma 2-pass (Xh·W + Xl·W), software-pipelined staging
// (prefetch next chunk's globals into registers during the mma loop).
// ---------------------------------------------------------------------------
#define PXH 0
#define PXL (128 * 144)
#define PWF (2 * 128 * 144)
#define SMP_TOTAL (PWF + 64 * 144)   // 46080

__global__ __launch_bounds__(256) void proj_mma_kernel(const float* __restrict__ x) {
    extern __shared__ __align__(16) char smem[];
    int ntile = blockIdx.x, m0 = blockIdx.y << 7;
    int t = threadIdx.x, wid = t >> 5, lane = t & 31;
    int qw = wid >> 1, hw = wid & 1;
    u32 sb = s2u(smem);

    int xrow = t >> 4, xc4 = t & 15;          // this thread's x slots (8 reps)
    int wrow = t >> 3, wc16 = t & 7;          // W slots (2 reps)

    float4 xv[8];
    uint4 wv[2];
    // prefetch kc=0
#pragma unroll
    for (int rep = 0; rep < 8; rep++)
        xv[rep] = *(const float4*)
            &x[(size_t)(m0 + ((rep * 256 + t) >> 4)) * CE + ((rep * 256 + t) & 15) * 4];
#pragma unroll
    for (int rep = 0; rep < 2; rep++)
        wv[rep] = *(const uint4*)
            &g_wtf[(size_t)(ntile * 64 + ((rep * 256 + t) >> 3)) * CE +
                   ((rep * 256 + t) & 7) * 8];

    float acc[2][4][4] = {};
#pragma unroll 1
    for (int kc = 0; kc < 16; kc++) {
        __syncthreads();   // previous mma reads complete
        // store prefetched x (with fp16 hi/lo split) and W to smem
#pragma unroll
        for (int rep = 0; rep < 8; rep++) {
            int li = rep * 256 + t;
            int row = li >> 4, c4 = li & 15;
            float4 v = xv[rep];
            __half2 h01 = __floats2half2_rn(v.x, v.y);
            __half2 h23 = __floats2half2_rn(v.z, v.w);
            __half2 l01 = __floats2half2_rn(v.x - __half2float(h01.x),
                                            v.y - __half2float(h01.y));
            __half2 l23 = __floats2half2_rn(v.z - __half2float(h23.x),
                                            v.w - __half2float(h23.y));
            *(__half2*)(smem + PXH + row * 144 + c4 * 8) = h01;
            *(__half2*)(smem + PXH + row * 144 + c4 * 8 + 4) = h23;
            *(__half2*)(smem + PXL + row * 144 + c4 * 8) = l01;
            *(__half2*)(smem + PXL + row * 144 + c4 * 8 + 4) = l23;
        }
#pragma unroll
        for (int rep = 0; rep < 2; rep++) {
            int li = rep * 256 + t;
            int row = li >> 3, c16 = li & 7;
            *(uint4*)(smem + PWF + row * 144 + c16 * 16) = wv[rep];
        }
        __syncthreads();

        // prefetch next chunk while mma runs
        if (kc < 15) {
            int k0n = (kc + 1) << 6;
#pragma unroll
            for (int rep = 0; rep < 8; rep++) {
                int li = rep * 256 + t;
                xv[rep] = *(const float4*)
                    &x[(size_t)(m0 + (li >> 4)) * CE + k0n + (li & 15) * 4];
            }
#pragma unroll
            for (int rep = 0; rep < 2; rep++) {
                int li = rep * 256 + t;
                wv[rep] = *(const uint4*)
                    &g_wtf[(size_t)(ntile * 64 + (li >> 3)) * CE + k0n + (li & 7) * 8];
            }
        }

#pragma unroll
        for (int kk = 0; kk < 4; kk++) {
            u32 ah[2][4], al[2][4];
#pragma unroll
            for (int tq = 0; tq < 2; tq++) {
                u32 aoff = (u32)((qw * 32 + tq * 16 + (lane & 15)) * 144 +
                                 (kk * 16 + ((lane >> 4) << 3)) * 2);
                ldsm4(ah[tq], sb + PXH + aoff);
                ldsm4(al[tq], sb + PXL + aoff);
            }
            u32 bf[2][4];
#pragma unroll
            for (int ng = 0; ng < 2; ng++) {
                u32 roff = (u32)((hw * 32 + ng * 16 + (lane & 7) +
                                  ((lane & 16) ? 8 : 0)) * 144 +
                                 (kk * 16 + ((lane & 8) ? 8 : 0)) * 2);
                ldsm4(bf[ng], sb + PWF + roff);
            }
#pragma unroll
            for (int tq = 0; tq < 2; tq++)
#pragma unroll
                for (int nt = 0; nt < 4; nt++) {
                    const u32* bb = bf[nt >> 1] + (nt & 1) * 2;
                    mma16816h(acc[tq][nt], ah[tq], bb);
                    mma16816h(acc[tq][nt], al[tq], bb);
                }
        }
    }

    int g = lane >> 2, tp = (lane & 3) << 1;
#pragma unroll
    for (int tq = 0; tq < 2; tq++) {
        int mA = m0 + qw * 32 + tq * 16 + g;
        int mB = mA + 8;
#pragma unroll
        for (int nt = 0; nt < 4; nt++) {
            int h = hw * 32 + nt * 8 + tp;
            float v0 = acc[tq][nt][0], v1 = acc[tq][nt][1];
            float v2 = acc[tq][nt][2], v3 = acc[tq][nt][3];
            if (ntile == 2) {
                *(float2*)&g_v[(size_t)mA * HD + h] = make_float2(v0, v1);
                *(float2*)&g_v[(size_t)mB * HD + h] = make_float2(v2, v3);
            } else {
                __half* dst = (ntile == 0) ? g_qf : g_kf;
                if (ntile == 0) {
                    v0 *= SCALE; v1 *= SCALE; v2 *= SCALE; v3 *= SCALE;
                }
                *(__half2*)&dst[(size_t)mA * HD + h] = __floats2half2_rn(v0, v1);
                *(__half2*)&dst[(size_t)mB * HD + h] = __floats2half2_rn(v2, v3);
            }
        }
    }
}

// ---------------------------------------------------------------------------
// Pass 2: score via f16 mma single pass (Qf·Kf). E -> one fp16 plane;
// d sums use fp16-rounded E (consistent-d). Coalesced smem-staged E stores.
// ---------------------------------------------------------------------------
#define OQF 0
#define OKF (128 * 144)
#define OBUF (2 * 128 * 144)
#define SMM_TOTAL (OBUF + 4 * 128 * 4)   // 38912
#define EPITCH 272

__global__ __launch_bounds__(256) void score_mma_kernel() {
    extern __shared__ __align__(16) char smem[];
    int b = blockIdx.y;
    int ti = blockIdx.x;
    int qt = (int)((sqrtf(8.f * (float)ti + 1.f) - 1.f) * 0.5f);
    while ((qt + 1) * (qt + 2) / 2 <= ti) qt++;
    while (qt * (qt + 1) / 2 > ti) qt--;
    int kt = ti - qt * (qt + 1) / 2;
    int q0 = qt << 7, k0 = kt << 7;
    int t = threadIdx.x, wid = t >> 5, lane = t & 31;

    {   // stage Qf + Kf
        int a = t >> 7, row = t & 127;
        const __half* src = (a == 0) ? g_qf + (size_t)(b * T_ + q0) * HD
                                     : g_kf + (size_t)(b * T_ + k0) * HD;
        const uint4* s = (const uint4*)(src + (size_t)row * HD);
        uint4* d = (uint4*)(smem + (a == 0 ? OQF : OKF) + row * 144);
#pragma unroll
        for (int c = 0; c < 8; c++) d[c] = s[c];
    }
    __syncthreads();

    int qw = wid >> 1, kw = wid & 1;
    u32 sb = s2u(smem);
    float acc[2][8][4] = {};

#pragma unroll
    for (int kk = 0; kk < 4; kk++) {
        u32 af[2][4];
#pragma unroll
        for (int tq = 0; tq < 2; tq++) {
            u32 aoff = (u32)((qw * 32 + tq * 16 + (lane & 15)) * 144 +
                             (kk * 16 + ((lane >> 4) << 3)) * 2);
            ldsm4(af[tq], sb + OQF + aoff);
        }
        u32 bf[4][4];
#pragma unroll
        for (int ng = 0; ng < 4; ng++) {
            u32 roff = (u32)((kw * 64 + ng * 16 + (lane & 7) +
                              ((lane & 16) ? 8 : 0)) * 144 +
                             (kk * 16 + ((lane & 8) ? 8 : 0)) * 2);
            ldsm4(bf[ng], sb + OKF + roff);
        }
#pragma unroll
        for (int tq = 0; tq < 2; tq++)
#pragma unroll
            for (int ng = 0; ng < 4; ng++)
#pragma unroll
                for (int hf = 0; hf < 2; hf++)
                    mma16816h(acc[tq][ng * 2 + hf], af[tq], bf[ng] + hf * 2);
    }

    __syncthreads();   // staging reads done; reuse smem for E tile

    char* efs = smem;                    // 128 x EPITCH (fp16 plane)
    int g = lane >> 2, tp = (lane & 3) << 1;
    bool diag = (kt == qt);
    float cs[8][2] = {};
#pragma unroll
    for (int tq = 0; tq < 2; tq++) {
        int rA = qw * 32 + tq * 16 + g;
        int rB = rA + 8;
#pragma unroll
        for (int nt = 0; nt < 8; nt++) {
            int col = kw * 64 + nt * 8 + tp;
            float e0 = fast_exp(acc[tq][nt][0]);
            float e1 = fast_exp(acc[tq][nt][1]);
            float e2 = fast_exp(acc[tq][nt][2]);
            float e3 = fast_exp(acc[tq][nt][3]);
            if (diag) {
                if (q0 + rA < k0 + col) e0 = 0.f;
                if (q0 + rA < k0 + col + 1) e1 = 0.f;
                if (q0 + rB < k0 + col) e2 = 0.f;
                if (q0 + rB < k0 + col + 1) e3 = 0.f;
            }
            __half2 hA = __floats2half2_rn(e0, e1);
            __half2 hB = __floats2half2_rn(e2, e3);
            *(__half2*)(efs + rA * EPITCH + col * 2) = hA;
            *(__half2*)(efs + rB * EPITCH + col * 2) = hB;
            cs[nt][0] += __half2float(hA.x) + __half2float(hB.x);
            cs[nt][1] += __half2float(hA.y) + __half2float(hB.y);
        }
    }
#pragma unroll
    for (int nt = 0; nt < 8; nt++)
#pragma unroll
        for (int j = 0; j < 2; j++) {
            float v = cs[nt][j];
            v += __shfl_xor_sync(0xffffffffu, v, 4);
            v += __shfl_xor_sync(0xffffffffu, v, 8);
            v += __shfl_xor_sync(0xffffffffu, v, 16);
            cs[nt][j] = v;
        }
    float* buf = (float*)(smem + OBUF);
    if (lane < 4) {
#pragma unroll
        for (int nt = 0; nt < 8; nt++) {
            buf[qw * 128 + kw * 64 + nt * 8 + ((lane & 3) << 1) + 0] = cs[nt][0];
            buf[qw * 128 + kw * 64 + nt * 8 + ((lane & 3) << 1) + 1] = cs[nt][1];
        }
    }
    __syncthreads();

    size_t gbase = (size_t)b * T_ * T_ + (size_t)q0 * T_ + k0;
#pragma unroll
    for (int rep = 0; rep < 8; rep++) {
        int li = rep * 256 + t;
        int row = li >> 4, c16 = li & 15;
        *(uint4*)&g_ef[gbase + (size_t)row * T_ + c16 * 8] =
            *(const uint4*)(efs + row * EPITCH + c16 * 16);
    }
    if (t < 128) {
        float s = buf[t] + buf[128 + t] + buf[256 + t] + buf[384 + t];
        g_dp[(size_t)((b << 5) + qt) * T_ + k0 + t] = s;
    }
}

// ---------------------------------------------------------------------------
// Pass 3: vprep with fused dinv: Vt = (V/d)^T fp16, [b][h][k]
// ---------------------------------------------------------------------------
__global__ __launch_bounds__(256) void vprep_kernel() {
    __shared__ __align__(16) float Vt[64][68];
    __shared__ float dinv_s[64];
    int k0 = blockIdx.x << 6, b = blockIdx.y;
    int t = threadIdx.x;

    if (t < 64) {
        int k = k0 + t;
        float s = 0.f;
        for (int qt = (k >> 7); qt < 32; qt++)
            s += g_dp[(size_t)((b << 5) + qt) * T_ + k];
        dinv_s[t] = 1.0f / s;
    }
    __syncthreads();
    {
        int k = t >> 2, hseg = (t & 3) << 4;
        float dinv = dinv_s[k];
        const float* src = &g_v[(size_t)(b * T_ + k0 + k) * HD + hseg];
#pragma unroll
        for (int u = 0; u < 4; u++) {
            float4 v = *(const float4*)&src[u * 4];
            Vt[hseg + u * 4 + 0][k] = v.x * dinv;
            Vt[hseg + u * 4 + 1][k] = v.y * dinv;
            Vt[hseg + u * 4 + 2][k] = v.z * dinv;
            Vt[hseg + u * 4 + 3][k] = v.w * dinv;
        }
    }
    __syncthreads();
    {
        int h = t >> 2, kseg = (t & 3) << 4;
        size_t dst = (size_t)(b * HD + h) * T_ + k0 + kseg;
#pragma unroll
        for (int u = 0; u < 4; u++) {
            __half2 p0 = __floats2half2_rn(Vt[h][kseg + u * 4 + 0],
                                           Vt[h][kseg + u * 4 + 1]);
            __half2 p1 = __floats2half2_rn(Vt[h][kseg + u * 4 + 2],
                                           Vt[h][kseg + u * 4 + 3]);
            *(__half2*)&g_vtf[dst + u * 4 + 0] = p0;
            *(__half2*)&g_vtf[dst + u * 4 + 2] = p1;
        }
    }
}

// ---------------------------------------------------------------------------
// Pass 4: out via f16 mma single pass: O = Ef @ Vtf.
// Tail-balanced: block (jj,s) handles its split-share of BOTH qt=jj and
// qt=31-jj tiles (uniform ~17 chunks). Grid (16, 4, 8).
// ---------------------------------------------------------------------------
#define OEF 0
#define OVF (128 * 144)
#define SMO_TOTAL (OVF + 64 * 144)   // 27648

__global__ __launch_bounds__(256) void out_mma_kernel() {
    extern __shared__ __align__(16) char smem[];
    int jj = blockIdx.x, s = blockIdx.y, b = blockIdx.z;
    int t = threadIdx.x, wid = t >> 5, lane = t & 31;
    int qw = wid >> 1, hw = wid & 1;
    u32 sb = s2u(smem);
    int g = lane >> 2, tp = (lane & 3) << 1;

#pragma unroll 1
    for (int half = 0; half < 2; half++) {
        int qt = half ? (31 - jj) : jj;
        int q0 = qt << 7;
        int nch = 2 * qt + 2;
        int lo = (s * nch) >> 2, hi = ((s + 1) * nch) >> 2;

        float acc[2][4][4] = {};
        for (int c = lo; c < hi; c++) {
            int k0 = c << 6;
            __syncthreads();
#pragma unroll
            for (int rep = 0; rep < 4; rep++) {
                int li = rep * 256 + t;
                int row = li >> 3, c16 = li & 7;
                *(uint4*)(smem + OEF + row * 144 + c16 * 16) = *(const uint4*)
                    &g_ef[((size_t)(b * T_ + q0 + row)) * T_ + k0 + c16 * 8];
            }
#pragma unroll
            for (int rep = 0; rep < 2; rep++) {
                int li = rep * 256 + t;
                int row = li >> 3, c16 = li & 7;
                *(uint4*)(smem + OVF + row * 144 + c16 * 16) = *(const uint4*)
                    &g_vtf[(size_t)(b * HD + row) * T_ + k0 + c16 * 8];
            }
            __syncthreads();

#pragma unroll
            for (int kk = 0; kk < 4; kk++) {
                u32 af[2][4];
#pragma unroll
                for (int tq = 0; tq < 2; tq++) {
                    u32 aoff = (u32)((qw * 32 + tq * 16 + (lane & 15)) * 144 +
                                     (kk * 16 + ((lane >> 4) << 3)) * 2);
                    ldsm4(af[tq], sb + OEF + aoff);
                }
                u32 bf[2][4];
#pragma unroll
                for (int ng = 0; ng < 2; ng++) {
                    u32 roff = (u32)((hw * 32 + ng * 16 + (lane & 7) +
                                      ((lane & 16) ? 8 : 0)) * 144 +
                                     (kk * 16 + ((lane & 8) ? 8 : 0)) * 2);
                    ldsm4(bf[ng], sb + OVF + roff);
                }
#pragma unroll
                for (int tq = 0; tq < 2; tq++)
#pragma unroll
                    for (int nt = 0; nt < 4; nt++)
                        mma16816h(acc[tq][nt], af[tq], bf[nt >> 1] + (nt & 1) * 2);
            }
        }

#pragma unroll
        for (int tq = 0; tq < 2; tq++) {
            int qrA = q0 + qw * 32 + tq * 16 + g;
#pragma unroll
            for (int nt = 0; nt < 4; nt++) {
                int h = hw * 32 + nt * 8 + tp;
                size_t base = (size_t)((s * B_ + b) * T_);
                *(float2*)&g_op[(base + qrA) * HD + h] =
                    make_float2(acc[tq][nt][0], acc[tq][nt][1]);
                *(float2*)&g_op[(base + qrA + 8) * HD + h] =
                    make_float2(acc[tq][nt][2], acc[tq][nt][3]);
            }
        }
        __syncthreads();   // partials written before next half re-stages
    }
}

// ---------------------------------------------------------------------------
// Pass 5: sum 4 split partials
// ---------------------------------------------------------------------------
__global__ void reduce_kernel(float* __restrict__ out) {
    const int N4 = B_ * T_ * HD / 4;
    int i = blockIdx.x * 256 + threadIdx.x;
    const float4* p = (const float4*)g_op;
    float4 a = p[i], b = p[i + N4], c = p[i + 2 * N4], d = p[i + 3 * N4];
    ((float4*)out)[i] = make_float4(a.x + b.x + c.x + d.x,
                                    a.y + b.y + c.y + d.y,
                                    a.z + b.z + c.z + d.z,
                                    a.w + b.w + c.w + d.w);
}

// ---------------------------------------------------------------------------
// inputs: x, Wk, Wq, Wv ; output fp32 [8,4096,64]
// ---------------------------------------------------------------------------
extern "C" void kernel_launch(void* const* d_in, const int* in_sizes, int n_in,
                              void* d_out, int out_size) {
    const float* x  = (const float*)d_in[0];
    const float* Wk = (const float*)d_in[1];
    const float* Wq = (const float*)d_in[2];
    const float* Wv = (const float*)d_in[3];
    float* out = (float*)d_out;

    cudaFuncSetAttribute(proj_mma_kernel,
        cudaFuncAttributeMaxDynamicSharedMemorySize, SMP_TOTAL);
    cudaFuncSetAttribute(score_mma_kernel,
        cudaFuncAttributeMaxDynamicSharedMemorySize, SMM_TOTAL);
    cudaFuncSetAttribute(out_mma_kernel,
        cudaFuncAttributeMaxDynamicSharedMemorySize, SMO_TOTAL);

    wsplit_kernel<<<768, 256>>>(Wq, Wk, Wv);
    proj_mma_kernel<<<dim3(3, 256), 256, SMP_TOTAL>>>(x);
    score_mma_kernel<<<dim3(528, 8), 256, SMM_TOTAL>>>();
    vprep_kernel<<<dim3(64, 8), 256>>>();
    out_mma_kernel<<<dim3(16, 4, 8), 256, SMO_TOTAL>>>();
    reduce_kernel<<<2048, 256>>>(out);
}